// round 11
// baseline (speedup 1.0000x reference)
#include <cuda_runtime.h>
#include <cuda_fp16.h>
#include <cstdint>

// Problem dims
#define MDIM 4096            // batch
#define GM   16384           // GEMM M = batch*4 (matrix rows)
#define GK   1024            // GEMM K = 2(re/im) * 128(f) * 4(t)
#define GN   1024            // GEMM N = 128(o) * 4(c) * 2(re/im)
#define BM 128
#define BN 128
#define BK 32
#define KTILES (GK / BK)     // 32
#define STAGES 4

// SMEM tile geometry: rows of 32 fp16 = 64B data, padded to 80B stride
#define ROW_BYTES 80
#define TILE_BYTES (128 * ROW_BYTES)          // 10240
#define STAGE_BYTES (2 * TILE_BYTES)          // A|B = 20480
#define SMEM_BYTES (STAGES * STAGE_BYTES)     // 81920  (also >= 128*132*4 = 67584 for epilogue)
#define EPI_STRIDE 132                        // floats per staged row

// static scratch (sanctioned __device__ globals): 32 + 2 MB
__device__ __align__(128) __half g_A2[(size_t)GM * GK];
__device__ __align__(128) __half g_B2[(size_t)GN * GK];

// ---------- compile-time gamma tables (Cl(4,1) -> M4(C)) ----------
// gamma1=s1(x)s1, gamma2=s1(x)s2, gamma3=s1(x)s3, gamma4=s2(x)I, gamma5=-i s3(x)I
struct Tables {
    int   fw_a[16][8];     // entry (r*4+c): the 8 blades hitting it
    int   fw_ph[16][8];    // their phases (0:+1 1:+i 2:-1 3:-i)
    int   inv_row[32][4];  // per blade a, column c: row
    int   inv_c8[32][4];   // column in the 4x8 (re,im interleaved) block
    float inv_sgn[32][4];  // sign * 1/4
    constexpr Tables() : fw_a(), fw_ph(), inv_row(), inv_c8(), inv_sgn() {
        int cnt[16] = {};
        for (int a = 0; a < 32; a++) {
            for (int c = 0; c < 4; c++) {
                int r = c, ph = 0;
                for (int bit = 4; bit >= 0; bit--) {   // rightmost factor acts first
                    if (!((a >> bit) & 1)) continue;
                    int nr = r, pa = 0;
                    if      (bit == 0) { nr = r ^ 3; pa = 0; }
                    else if (bit == 1) { nr = r ^ 3; pa = (r & 1) ? 3 : 1; }
                    else if (bit == 2) { nr = r ^ 2; pa = (r & 1) ? 2 : 0; }
                    else if (bit == 3) { nr = r ^ 2; pa = (r & 2) ? 3 : 1; }
                    else               { nr = r;     pa = (r & 2) ? 1 : 3; }
                    r = nr; ph = (ph + pa) & 3;
                }
                int idx = r * 4 + c;
                fw_a[idx][cnt[idx]] = a;
                fw_ph[idx][cnt[idx]] = ph;
                cnt[idx]++;
                inv_row[a][c] = r;
                inv_c8[a][c]  = c * 2 + (ph & 1);
                inv_sgn[a][c] = (ph >= 2) ? -0.25f : 0.25f;
            }
        }
    }
};
__constant__ Tables TB = Tables();

// ---------------- helpers ----------------
__device__ __forceinline__ uint32_t smem_u32(const void* p) {
    uint32_t a;
    asm("{ .reg .u64 t; cvta.to.shared.u64 t, %1; cvt.u32.u64 %0, t; }" : "=r"(a) : "l"(p));
    return a;
}
__device__ __forceinline__ void cp_async16(uint32_t s, const void* g) {
    asm volatile("cp.async.cg.shared.global [%0], [%1], 16;" :: "r"(s), "l"(g));
}
#define CP_COMMIT() asm volatile("cp.async.commit_group;" ::: "memory")
#define CP_WAIT2()  asm volatile("cp.async.wait_group 2;" ::: "memory")

__device__ __forceinline__ void ldsm4(uint32_t (&r)[4], uint32_t addr) {
    asm volatile("ldmatrix.sync.aligned.m8n8.x4.shared.b16 {%0,%1,%2,%3}, [%4];"
                 : "=r"(r[0]), "=r"(r[1]), "=r"(r[2]), "=r"(r[3]) : "r"(addr));
}
__device__ __forceinline__ void mma16816(float (&c)[4], const uint32_t (&a)[4],
                                         uint32_t b0, uint32_t b1) {
    asm volatile("mma.sync.aligned.m16n8k16.row.col.f32.f16.f16.f32 "
                 "{%0,%1,%2,%3}, {%4,%5,%6,%7}, {%8,%9}, {%0,%1,%2,%3};"
                 : "+f"(c[0]), "+f"(c[1]), "+f"(c[2]), "+f"(c[3])
                 : "r"(a[0]), "r"(a[1]), "r"(a[2]), "r"(a[3]), "r"(b0), "r"(b1));
}
__device__ __forceinline__ uint32_t pack2h(float a, float b) {
    __half2 h = make_half2(__float2half_rn(a), __float2half_rn(b));
    return *reinterpret_cast<uint32_t*>(&h);
}

// ---------------- pre-kernels ----------------
// x[b,f,0..31] -> X matrix entries; A2[4b+r, u*512 + f*4 + t]
// SMEM-staged: coalesced GMEM loads, padded rows (33 words) for conflict-free
// per-thread row reads in the compute phase.
#define XS_PAD 33
__global__ __launch_bounds__(256, 2) void k_build_A(const float* __restrict__ x) {
    __shared__ float xs[256 * XS_PAD];
    const int tid = threadIdx.x;
    const unsigned tau0 = blockIdx.x * 256u;       // first (b,f) row of this block

    // coalesced load: 256 rows x 128 B = 32 KB
    const float4* src = (const float4*)(x + (size_t)tau0 * 32);
#pragma unroll
    for (int j = 0; j < 8; j++) {
        int idx = j * 256 + tid;                   // 0..2047 float4s
        float4 v = src[idx];
        int row = idx >> 3;
        int w = (idx & 7) * 4;
        float* d = xs + row * XS_PAD + w;
        d[0] = v.x; d[1] = v.y; d[2] = v.z; d[3] = v.w;
    }
    __syncthreads();

    const unsigned tau = tau0 + tid;
    const unsigned b = tau >> 7, f = tau & 127u;
    float xv[32];
    const float* myrow = xs + tid * XS_PAD;
#pragma unroll
    for (int a = 0; a < 32; a++) xv[a] = myrow[a];

#pragma unroll
    for (int r = 0; r < 4; r++) {
        float re[4], im[4];
#pragma unroll
        for (int t = 0; t < 4; t++) {
            float rr = 0.f, ii = 0.f;
#pragma unroll
            for (int e = 0; e < 8; e++) {
                int a  = TB.fw_a[r * 4 + t][e];
                int ph = TB.fw_ph[r * 4 + t][e];
                float v = xv[a];
                if (ph == 0) rr += v; else if (ph == 1) ii += v;
                else if (ph == 2) rr -= v; else ii -= v;
            }
            re[t] = rr; im[t] = ii;
        }
        size_t row = (size_t)(b * 4 + r) * GK;
        uint2 pre = make_uint2(pack2h(re[0], re[1]), pack2h(re[2], re[3]));
        uint2 pim = make_uint2(pack2h(im[0], im[1]), pack2h(im[2], im[3]));
        *(uint2*)(g_A2 + row + f * 4)       = pre;
        *(uint2*)(g_A2 + row + 512 + f * 4) = pim;
    }
}

// W[o,f,0..31] -> Wm; B2[n = o*8 + c*2 + v, u*512 + f*4 + t]
__global__ void k_build_w2(const float* __restrict__ w) {
    unsigned tau = blockIdx.x * blockDim.x + threadIdx.x;   // 0 .. 16383
    unsigned o = tau >> 7, f = tau & 127u;
    float wv[32];
    const float4* wp = (const float4*)(w + ((size_t)o * 128 + f) * 32);
#pragma unroll
    for (int q = 0; q < 8; q++) {
        float4 v = wp[q];
        wv[q * 4 + 0] = v.x; wv[q * 4 + 1] = v.y; wv[q * 4 + 2] = v.z; wv[q * 4 + 3] = v.w;
    }
    float re[4][4], im[4][4];   // [t][c]
#pragma unroll
    for (int t = 0; t < 4; t++)
#pragma unroll
        for (int c = 0; c < 4; c++) {
            float rr = 0.f, ii = 0.f;
#pragma unroll
            for (int e = 0; e < 8; e++) {
                int a  = TB.fw_a[t * 4 + c][e];
                int ph = TB.fw_ph[t * 4 + c][e];
                float v = wv[a];
                if (ph == 0) rr += v; else if (ph == 1) ii += v;
                else if (ph == 2) rr -= v; else ii -= v;
            }
            re[t][c] = rr; im[t][c] = ii;
        }
#pragma unroll
    for (int c = 0; c < 4; c++)
#pragma unroll
        for (int v = 0; v < 2; v++) {
            size_t row = (size_t)(o * 8 + c * 2 + v) * GK;
            float u0[4], u1[4];
#pragma unroll
            for (int t = 0; t < 4; t++) {
                u0[t] = v ? im[t][c] :  re[t][c];
                u1[t] = v ? re[t][c] : -im[t][c];
            }
            *(uint2*)(g_B2 + row + f * 4)       = make_uint2(pack2h(u0[0], u0[1]), pack2h(u0[2], u0[3]));
            *(uint2*)(g_B2 + row + 512 + f * 4) = make_uint2(pack2h(u1[0], u1[1]), pack2h(u1[2], u1[3]));
        }
}

// ---------------- GEMM (mma.sync fp16) with fused epilogue ----------------
__device__ __forceinline__ void load_stage(uint32_t sbase, int slot, int m0, int n0,
                                           int k0, int tid) {
    const uint32_t so = sbase + slot * STAGE_BYTES;
    const __half* srcs[2] = {g_A2, g_B2};
    const int rows[2] = {m0, n0};
#pragma unroll
    for (int t2 = 0; t2 < 2; t2++) {
        const char* gb = (const char*)(srcs[t2] + (size_t)rows[t2] * GK + k0);
        uint32_t sdst = so + t2 * TILE_BYTES;
#pragma unroll
        for (int j = 0; j < 2; j++) {
            int chunk = tid * 2 + j;          // 0..511
            int r = chunk >> 2;               // row 0..127
            int cc = chunk & 3;               // 16B chunk in row
            cp_async16(sdst + r * ROW_BYTES + cc * 16,
                       gb + (size_t)r * (GK * 2) + cc * 16);
        }
    }
}

__global__ __launch_bounds__(256, 2) void gemm_kernel(float* __restrict__ out) {
    extern __shared__ char smem[];
    const uint32_t sb = smem_u32(smem);
    const int tid = threadIdx.x;
    const int wid = tid >> 5;
    const int lane = tid & 31;
    const int warp_m = wid & 1;               // 2 x 64 rows
    const int warp_n = wid >> 1;              // 4 x 32 cols
    const int m0 = blockIdx.y * BM;
    const int n0 = blockIdx.x * BN;

    float acc[4][4][4];
#pragma unroll
    for (int a = 0; a < 4; a++)
#pragma unroll
        for (int b = 0; b < 4; b++)
#pragma unroll
            for (int c = 0; c < 4; c++) acc[a][b][c] = 0.f;

    for (int s = 0; s < STAGES - 1; s++) {
        load_stage(sb, s, m0, n0, s * BK, tid);
        CP_COMMIT();
    }

    const int lrow = lane & 15;
    const int lhalf = lane >> 4;

    for (int t = 0; t < KTILES; t++) {
        CP_WAIT2();
        __syncthreads();

        if (t + STAGES - 1 < KTILES)
            load_stage(sb, (t + STAGES - 1) & 3, m0, n0, (t + STAGES - 1) * BK, tid);
        CP_COMMIT();

        const uint32_t st = sb + (t & 3) * STAGE_BYTES;
        const uint32_t Ah = st;
        const uint32_t Bh = st + TILE_BYTES;

#pragma unroll
        for (int ks = 0; ks < 2; ks++) {
            const int cc = ks * 2 + lhalf;
            uint32_t a[4][4];
#pragma unroll
            for (int mt = 0; mt < 4; mt++) {
                const int r = warp_m * 64 + mt * 16 + lrow;
                ldsm4(a[mt], Ah + r * ROW_BYTES + cc * 16);
            }
            uint32_t b0[4], b1[4];
#pragma unroll
            for (int np = 0; np < 2; np++) {
                const int r = warp_n * 32 + np * 16 + lrow;
                uint32_t q[4];
                ldsm4(q, Bh + r * ROW_BYTES + cc * 16);
                b0[2 * np] = q[0]; b0[2 * np + 1] = q[1];
                b1[2 * np] = q[2]; b1[2 * np + 1] = q[3];
            }
#pragma unroll
            for (int mt = 0; mt < 4; mt++)
#pragma unroll
                for (int nt = 0; nt < 4; nt++)
                    mma16816(acc[mt][nt], a[mt], b0[nt], b1[nt]);
        }
        __syncthreads();
    }

    // drain async pipe before repurposing SMEM
    asm volatile("cp.async.wait_group 0;" ::: "memory");
    __syncthreads();

    // ---- fused epilogue ----
    float* cs = (float*)smem;
    const int gid = lane >> 2;
    const int qid = lane & 3;
#pragma unroll
    for (int mt = 0; mt < 4; mt++) {
        const int r0 = warp_m * 64 + mt * 16 + gid;
        const int r1 = r0 + 8;
#pragma unroll
        for (int nt = 0; nt < 4; nt++) {
            const int col = warp_n * 32 + nt * 8 + qid * 2;
            cs[r0 * EPI_STRIDE + col]     = acc[mt][nt][0];
            cs[r0 * EPI_STRIDE + col + 1] = acc[mt][nt][1];
            cs[r1 * EPI_STRIDE + col]     = acc[mt][nt][2];
            cs[r1 * EPI_STRIDE + col + 1] = acc[mt][nt][3];
        }
    }
    __syncthreads();

    const int b_base = m0 >> 2;    // global batch base of this tile
    const int o_base = n0 >> 3;    // global o base of this tile
#pragma unroll
    for (int it = 0; it < 2; it++) {
        const int blk = tid * 2 + it;          // 0..511
        const int b_local = blk >> 4;          // 0..31
        const int o_local = blk & 15;          // 0..15
        float blkv[4][8];
#pragma unroll
        for (int r = 0; r < 4; r++) {
            const float* rp = cs + (b_local * 4 + r) * EPI_STRIDE + o_local * 8;
#pragma unroll
            for (int c8 = 0; c8 < 8; c8++) blkv[r][c8] = rp[c8];
        }
        float y[32];
        float ssum = 0.f;
#pragma unroll
        for (int a = 0; a < 32; a++) {
            float s = 0.f;
#pragma unroll
            for (int c = 0; c < 4; c++)
                s += TB.inv_sgn[a][c] * blkv[TB.inv_row[a][c]][TB.inv_c8[a][c]];
            y[a] = s;
            ssum += s * s;
        }
        const float inv = rsqrtf(ssum + 1e-6f);
        float* op = out + (size_t)(b_base + b_local) * 4096 + (o_base + o_local) * 32;
#pragma unroll
        for (int a = 0; a < 32; a += 4)
            *(float4*)(op + a) = make_float4(y[a] * inv, y[a + 1] * inv,
                                             y[a + 2] * inv, y[a + 3] * inv);
    }
}

// ---------------- launch ----------------
extern "C" void kernel_launch(void* const* d_in, const int* in_sizes, int n_in,
                              void* d_out, int out_size) {
    (void)in_sizes; (void)n_in; (void)out_size;
    const float* x = (const float*)d_in[0];
    const float* w = (const float*)d_in[1];
    float* out = (float*)d_out;

    k_build_A<<<2048, 256>>>(x);
    k_build_w2<<<16384 / 256, 256>>>(w);

    static bool attr_set = false;
    if (!attr_set) {
        cudaFuncSetAttribute(gemm_kernel, cudaFuncAttributeMaxDynamicSharedMemorySize,
                             SMEM_BYTES);
        attr_set = true;
    }
    gemm_kernel<<<dim3(GN / BN, GM / BM), 256, SMEM_BYTES>>>(out);
}

// round 12
// speedup vs baseline: 1.0027x; 1.0027x over previous
#include <cuda_runtime.h>
#include <cuda_fp16.h>
#include <cstdint>

// Problem dims
#define MDIM 4096            // batch
#define GM   16384           // GEMM M = batch*4 (matrix rows)
#define GK   1024            // GEMM K = 2(re/im) * 128(f) * 4(t)
#define GN   1024            // GEMM N = 128(o) * 4(c) * 2(re/im)
#define BM 128
#define BN 128
#define BK 32
#define KTILES (GK / BK)     // 32
#define STAGES 4

// SMEM tile geometry: rows of 32 fp16 = 64B data, padded to 80B stride
#define ROW_BYTES 80
#define TILE_BYTES (128 * ROW_BYTES)          // 10240
#define STAGE_BYTES (2 * TILE_BYTES)          // A|B = 20480
#define SMEM_BYTES (STAGES * STAGE_BYTES)     // 81920  (also >= 128*132*4 = 67584 for epilogue)
#define EPI_STRIDE 132                        // floats per staged row

// static scratch (sanctioned __device__ globals): 32 + 2 MB
__device__ __align__(128) __half g_A2[(size_t)GM * GK];
__device__ __align__(128) __half g_B2[(size_t)GN * GK];

// ---------- compile-time gamma tables (Cl(4,1) -> M4(C)) ----------
// gamma1=s1(x)s1, gamma2=s1(x)s2, gamma3=s1(x)s3, gamma4=s2(x)I, gamma5=-i s3(x)I
struct Tables {
    int   fw_a[16][8];     // entry (r*4+c): the 8 blades hitting it
    int   fw_ph[16][8];    // their phases (0:+1 1:+i 2:-1 3:-i)
    int   inv_row[32][4];  // per blade a, column c: row
    int   inv_c8[32][4];   // column in the 4x8 (re,im interleaved) block
    float inv_sgn[32][4];  // sign * 1/4
    constexpr Tables() : fw_a(), fw_ph(), inv_row(), inv_c8(), inv_sgn() {
        int cnt[16] = {};
        for (int a = 0; a < 32; a++) {
            for (int c = 0; c < 4; c++) {
                int r = c, ph = 0;
                for (int bit = 4; bit >= 0; bit--) {   // rightmost factor acts first
                    if (!((a >> bit) & 1)) continue;
                    int nr = r, pa = 0;
                    if      (bit == 0) { nr = r ^ 3; pa = 0; }
                    else if (bit == 1) { nr = r ^ 3; pa = (r & 1) ? 3 : 1; }
                    else if (bit == 2) { nr = r ^ 2; pa = (r & 1) ? 2 : 0; }
                    else if (bit == 3) { nr = r ^ 2; pa = (r & 2) ? 3 : 1; }
                    else               { nr = r;     pa = (r & 2) ? 1 : 3; }
                    r = nr; ph = (ph + pa) & 3;
                }
                int idx = r * 4 + c;
                fw_a[idx][cnt[idx]] = a;
                fw_ph[idx][cnt[idx]] = ph;
                cnt[idx]++;
                inv_row[a][c] = r;
                inv_c8[a][c]  = c * 2 + (ph & 1);
                inv_sgn[a][c] = (ph >= 2) ? -0.25f : 0.25f;
            }
        }
    }
};
__constant__ Tables TB = Tables();

// ---------------- helpers ----------------
__device__ __forceinline__ uint32_t smem_u32(const void* p) {
    uint32_t a;
    asm("{ .reg .u64 t; cvta.to.shared.u64 t, %1; cvt.u32.u64 %0, t; }" : "=r"(a) : "l"(p));
    return a;
}
__device__ __forceinline__ void cp_async16(uint32_t s, const void* g) {
    asm volatile("cp.async.cg.shared.global [%0], [%1], 16;" :: "r"(s), "l"(g));
}
#define CP_COMMIT() asm volatile("cp.async.commit_group;" ::: "memory")
#define CP_WAIT2()  asm volatile("cp.async.wait_group 2;" ::: "memory")
#define CP_WAIT0()  asm volatile("cp.async.wait_group 0;" ::: "memory")

__device__ __forceinline__ void ldsm4(uint32_t (&r)[4], uint32_t addr) {
    asm volatile("ldmatrix.sync.aligned.m8n8.x4.shared.b16 {%0,%1,%2,%3}, [%4];"
                 : "=r"(r[0]), "=r"(r[1]), "=r"(r[2]), "=r"(r[3]) : "r"(addr));
}
__device__ __forceinline__ void mma16816(float (&c)[4], const uint32_t (&a)[4],
                                         uint32_t b0, uint32_t b1) {
    asm volatile("mma.sync.aligned.m16n8k16.row.col.f32.f16.f16.f32 "
                 "{%0,%1,%2,%3}, {%4,%5,%6,%7}, {%8,%9}, {%0,%1,%2,%3};"
                 : "+f"(c[0]), "+f"(c[1]), "+f"(c[2]), "+f"(c[3])
                 : "r"(a[0]), "r"(a[1]), "r"(a[2]), "r"(a[3]), "r"(b0), "r"(b1));
}
__device__ __forceinline__ uint32_t pack2h(float a, float b) {
    __half2 h = make_half2(__float2half_rn(a), __float2half_rn(b));
    return *reinterpret_cast<uint32_t*>(&h);
}

// ---------------- pre-kernels ----------------
// x[b,f,0..31] -> X matrix entries; A2[4b+r, u*512 + f*4 + t]
// cp.async-staged coalesced loads; row stride 36 floats (144B, 16B-aligned) so
// read-back is 8x LDS.128, conflict-free: banks (4l+4c) mod 32 distinct per phase.
#define XPAD 36
__global__ __launch_bounds__(256) void k_build_A(const float* __restrict__ x) {
    __shared__ __align__(16) float xs[256 * XPAD];   // 36864 B
    const int tid = threadIdx.x;
    const unsigned tau0 = blockIdx.x * 256u;         // first (b,f) row of this block
    const uint32_t sbase = smem_u32(xs);

    // coalesced cp.async: 256 rows x 128 B = 32 KB, 16B chunks
    const float4* src = (const float4*)(x + (size_t)tau0 * 32);
#pragma unroll
    for (int j = 0; j < 8; j++) {
        int idx = j * 256 + tid;                     // float4 index 0..2047
        int row = idx >> 3;
        int c = idx & 7;
        cp_async16(sbase + (row * XPAD + c * 4) * 4, src + idx);
    }
    CP_COMMIT();
    CP_WAIT0();
    __syncthreads();

    const unsigned tau = tau0 + tid;
    const unsigned b = tau >> 7, f = tau & 127u;
    float xv[32];
    const float4* myrow = (const float4*)(xs + tid * XPAD);
#pragma unroll
    for (int c = 0; c < 8; c++) {
        float4 v = myrow[c];
        xv[c * 4 + 0] = v.x; xv[c * 4 + 1] = v.y; xv[c * 4 + 2] = v.z; xv[c * 4 + 3] = v.w;
    }

#pragma unroll
    for (int r = 0; r < 4; r++) {
        float re[4], im[4];
#pragma unroll
        for (int t = 0; t < 4; t++) {
            float rr = 0.f, ii = 0.f;
#pragma unroll
            for (int e = 0; e < 8; e++) {
                int a  = TB.fw_a[r * 4 + t][e];
                int ph = TB.fw_ph[r * 4 + t][e];
                float v = xv[a];
                if (ph == 0) rr += v; else if (ph == 1) ii += v;
                else if (ph == 2) rr -= v; else ii -= v;
            }
            re[t] = rr; im[t] = ii;
        }
        size_t row = (size_t)(b * 4 + r) * GK;
        uint2 pre = make_uint2(pack2h(re[0], re[1]), pack2h(re[2], re[3]));
        uint2 pim = make_uint2(pack2h(im[0], im[1]), pack2h(im[2], im[3]));
        *(uint2*)(g_A2 + row + f * 4)       = pre;
        *(uint2*)(g_A2 + row + 512 + f * 4) = pim;
    }
}

// W[o,f,0..31] -> Wm; B2[n = o*8 + c*2 + v, u*512 + f*4 + t]
__global__ void k_build_w2(const float* __restrict__ w) {
    unsigned tau = blockIdx.x * blockDim.x + threadIdx.x;   // 0 .. 16383
    unsigned o = tau >> 7, f = tau & 127u;
    float wv[32];
    const float4* wp = (const float4*)(w + ((size_t)o * 128 + f) * 32);
#pragma unroll
    for (int q = 0; q < 8; q++) {
        float4 v = wp[q];
        wv[q * 4 + 0] = v.x; wv[q * 4 + 1] = v.y; wv[q * 4 + 2] = v.z; wv[q * 4 + 3] = v.w;
    }
    float re[4][4], im[4][4];   // [t][c]
#pragma unroll
    for (int t = 0; t < 4; t++)
#pragma unroll
        for (int c = 0; c < 4; c++) {
            float rr = 0.f, ii = 0.f;
#pragma unroll
            for (int e = 0; e < 8; e++) {
                int a  = TB.fw_a[t * 4 + c][e];
                int ph = TB.fw_ph[t * 4 + c][e];
                float v = wv[a];
                if (ph == 0) rr += v; else if (ph == 1) ii += v;
                else if (ph == 2) rr -= v; else ii -= v;
            }
            re[t][c] = rr; im[t][c] = ii;
        }
#pragma unroll
    for (int c = 0; c < 4; c++)
#pragma unroll
        for (int v = 0; v < 2; v++) {
            size_t row = (size_t)(o * 8 + c * 2 + v) * GK;
            float u0[4], u1[4];
#pragma unroll
            for (int t = 0; t < 4; t++) {
                u0[t] = v ? im[t][c] :  re[t][c];
                u1[t] = v ? re[t][c] : -im[t][c];
            }
            *(uint2*)(g_B2 + row + f * 4)       = make_uint2(pack2h(u0[0], u0[1]), pack2h(u0[2], u0[3]));
            *(uint2*)(g_B2 + row + 512 + f * 4) = make_uint2(pack2h(u1[0], u1[1]), pack2h(u1[2], u1[3]));
        }
}

// ---------------- GEMM (mma.sync fp16) with fused epilogue ----------------
__device__ __forceinline__ void load_stage(uint32_t sbase, int slot, int m0, int n0,
                                           int k0, int tid) {
    const uint32_t so = sbase + slot * STAGE_BYTES;
    const __half* srcs[2] = {g_A2, g_B2};
    const int rows[2] = {m0, n0};
#pragma unroll
    for (int t2 = 0; t2 < 2; t2++) {
        const char* gb = (const char*)(srcs[t2] + (size_t)rows[t2] * GK + k0);
        uint32_t sdst = so + t2 * TILE_BYTES;
#pragma unroll
        for (int j = 0; j < 2; j++) {
            int chunk = tid * 2 + j;          // 0..511
            int r = chunk >> 2;               // row 0..127
            int cc = chunk & 3;               // 16B chunk in row
            cp_async16(sdst + r * ROW_BYTES + cc * 16,
                       gb + (size_t)r * (GK * 2) + cc * 16);
        }
    }
}

__global__ __launch_bounds__(256, 2) void gemm_kernel(float* __restrict__ out) {
    extern __shared__ char smem[];
    const uint32_t sb = smem_u32(smem);
    const int tid = threadIdx.x;
    const int wid = tid >> 5;
    const int lane = tid & 31;
    const int warp_m = wid & 1;               // 2 x 64 rows
    const int warp_n = wid >> 1;              // 4 x 32 cols
    const int m0 = blockIdx.y * BM;
    const int n0 = blockIdx.x * BN;

    float acc[4][4][4];
#pragma unroll
    for (int a = 0; a < 4; a++)
#pragma unroll
        for (int b = 0; b < 4; b++)
#pragma unroll
            for (int c = 0; c < 4; c++) acc[a][b][c] = 0.f;

    for (int s = 0; s < STAGES - 1; s++) {
        load_stage(sb, s, m0, n0, s * BK, tid);
        CP_COMMIT();
    }

    const int lrow = lane & 15;
    const int lhalf = lane >> 4;

    for (int t = 0; t < KTILES; t++) {
        CP_WAIT2();
        __syncthreads();

        if (t + STAGES - 1 < KTILES)
            load_stage(sb, (t + STAGES - 1) & 3, m0, n0, (t + STAGES - 1) * BK, tid);
        CP_COMMIT();

        const uint32_t st = sb + (t & 3) * STAGE_BYTES;
        const uint32_t Ah = st;
        const uint32_t Bh = st + TILE_BYTES;

#pragma unroll
        for (int ks = 0; ks < 2; ks++) {
            const int cc = ks * 2 + lhalf;
            uint32_t a[4][4];
#pragma unroll
            for (int mt = 0; mt < 4; mt++) {
                const int r = warp_m * 64 + mt * 16 + lrow;
                ldsm4(a[mt], Ah + r * ROW_BYTES + cc * 16);
            }
            uint32_t b0[4], b1[4];
#pragma unroll
            for (int np = 0; np < 2; np++) {
                const int r = warp_n * 32 + np * 16 + lrow;
                uint32_t q[4];
                ldsm4(q, Bh + r * ROW_BYTES + cc * 16);
                b0[2 * np] = q[0]; b0[2 * np + 1] = q[1];
                b1[2 * np] = q[2]; b1[2 * np + 1] = q[3];
            }
#pragma unroll
            for (int mt = 0; mt < 4; mt++)
#pragma unroll
                for (int nt = 0; nt < 4; nt++)
                    mma16816(acc[mt][nt], a[mt], b0[nt], b1[nt]);
        }
        __syncthreads();
    }

    // drain async pipe before repurposing SMEM
    CP_WAIT0();
    __syncthreads();

    // ---- fused epilogue ----
    float* cs = (float*)smem;
    const int gid = lane >> 2;
    const int qid = lane & 3;
#pragma unroll
    for (int mt = 0; mt < 4; mt++) {
        const int r0 = warp_m * 64 + mt * 16 + gid;
        const int r1 = r0 + 8;
#pragma unroll
        for (int nt = 0; nt < 4; nt++) {
            const int col = warp_n * 32 + nt * 8 + qid * 2;
            cs[r0 * EPI_STRIDE + col]     = acc[mt][nt][0];
            cs[r0 * EPI_STRIDE + col + 1] = acc[mt][nt][1];
            cs[r1 * EPI_STRIDE + col]     = acc[mt][nt][2];
            cs[r1 * EPI_STRIDE + col + 1] = acc[mt][nt][3];
        }
    }
    __syncthreads();

    const int b_base = m0 >> 2;    // global batch base of this tile
    const int o_base = n0 >> 3;    // global o base of this tile
#pragma unroll
    for (int it = 0; it < 2; it++) {
        const int blk = tid * 2 + it;          // 0..511
        const int b_local = blk >> 4;          // 0..31
        const int o_local = blk & 15;          // 0..15
        float blkv[4][8];
#pragma unroll
        for (int r = 0; r < 4; r++) {
            const float* rp = cs + (b_local * 4 + r) * EPI_STRIDE + o_local * 8;
#pragma unroll
            for (int c8 = 0; c8 < 8; c8++) blkv[r][c8] = rp[c8];
        }
        float y[32];
        float ssum = 0.f;
#pragma unroll
        for (int a = 0; a < 32; a++) {
            float s = 0.f;
#pragma unroll
            for (int c = 0; c < 4; c++)
                s += TB.inv_sgn[a][c] * blkv[TB.inv_row[a][c]][TB.inv_c8[a][c]];
            y[a] = s;
            ssum += s * s;
        }
        const float inv = rsqrtf(ssum + 1e-6f);
        float* op = out + (size_t)(b_base + b_local) * 4096 + (o_base + o_local) * 32;
#pragma unroll
        for (int a = 0; a < 32; a += 4)
            *(float4*)(op + a) = make_float4(y[a] * inv, y[a + 1] * inv,
                                             y[a + 2] * inv, y[a + 3] * inv);
    }
}

// ---------------- launch ----------------
extern "C" void kernel_launch(void* const* d_in, const int* in_sizes, int n_in,
                              void* d_out, int out_size) {
    (void)in_sizes; (void)n_in; (void)out_size;
    const float* x = (const float*)d_in[0];
    const float* w = (const float*)d_in[1];
    float* out = (float*)d_out;

    k_build_A<<<2048, 256>>>(x);
    k_build_w2<<<16384 / 256, 256>>>(w);

    static bool attr_set = false;
    if (!attr_set) {
        cudaFuncSetAttribute(gemm_kernel, cudaFuncAttributeMaxDynamicSharedMemorySize,
                             SMEM_BYTES);
        attr_set = true;
    }
    gemm_kernel<<<dim3(GN / BN, GM / BM), 256, SMEM_BYTES>>>(out);
}

// round 17
// speedup vs baseline: 1.4612x; 1.4573x over previous
#include <cuda_runtime.h>
#include <cuda_fp16.h>
#include <cstdint>

// Problem dims
#define MDIM 4096            // batch
#define GM   16384           // GEMM M = batch*4 (matrix rows)
#define GK   1024            // GEMM K = 2(re/im) * 128(f) * 4(t)
#define GN   1024            // GEMM N = 128(o) * 4(c) * 2(re/im)
#define BM 128
#define BN 128
#define BK 32
#define KTILES (GK / BK)     // 32
#define STAGES 4

// SMEM tile geometry: rows of 32 fp16 = 64B data, padded to 80B stride
#define ROW_BYTES 80
#define TILE_BYTES (128 * ROW_BYTES)          // 10240
#define STAGE_BYTES (2 * TILE_BYTES)          // A|B = 20480
#define SMEM_BYTES (STAGES * STAGE_BYTES)     // 81920  (also >= 128*132*4 = 67584 for epilogue)
#define EPI_STRIDE 132                        // floats per staged row

// static scratch (sanctioned __device__ globals): 32 + 2 MB
__device__ __align__(128) __half g_A2[(size_t)GM * GK];
__device__ __align__(128) __half g_B2[(size_t)GN * GK];

// ---------- compile-time gamma tables (Cl(4,1) -> M4(C)) ----------
// gamma1=s1(x)s1, gamma2=s1(x)s2, gamma3=s1(x)s3, gamma4=s2(x)I, gamma5=-i s3(x)I
// Instantiated as a function-local constexpr object inside each device function
// and indexed only with unroll-constant indices, so every lookup and
// phase-branch folds at compile time: no LDC, no branches.
struct Tables {
    int   fw_a[16][8];     // entry (r*4+c): the 8 blades hitting it
    int   fw_ph[16][8];    // their phases (0:+1 1:+i 2:-1 3:-i)
    int   inv_row[32][4];  // per blade a, column c: row
    int   inv_c8[32][4];   // column in the 4x8 (re,im interleaved) block
    float inv_sgn[32][4];  // sign * 1/4
    constexpr Tables() : fw_a(), fw_ph(), inv_row(), inv_c8(), inv_sgn() {
        int cnt[16] = {};
        for (int a = 0; a < 32; a++) {
            for (int c = 0; c < 4; c++) {
                int r = c, ph = 0;
                for (int bit = 4; bit >= 0; bit--) {   // rightmost factor acts first
                    if (!((a >> bit) & 1)) continue;
                    int nr = r, pa = 0;
                    if      (bit == 0) { nr = r ^ 3; pa = 0; }
                    else if (bit == 1) { nr = r ^ 3; pa = (r & 1) ? 3 : 1; }
                    else if (bit == 2) { nr = r ^ 2; pa = (r & 1) ? 2 : 0; }
                    else if (bit == 3) { nr = r ^ 2; pa = (r & 2) ? 3 : 1; }
                    else               { nr = r;     pa = (r & 2) ? 1 : 3; }
                    r = nr; ph = (ph + pa) & 3;
                }
                int idx = r * 4 + c;
                fw_a[idx][cnt[idx]] = a;
                fw_ph[idx][cnt[idx]] = ph;
                cnt[idx]++;
                inv_row[a][c] = r;
                inv_c8[a][c]  = c * 2 + (ph & 1);
                inv_sgn[a][c] = (ph >= 2) ? -0.25f : 0.25f;
            }
        }
    }
};

// ---------------- helpers ----------------
__device__ __forceinline__ uint32_t smem_u32(const void* p) {
    uint32_t a;
    asm("{ .reg .u64 t; cvta.to.shared.u64 t, %1; cvt.u32.u64 %0, t; }" : "=r"(a) : "l"(p));
    return a;
}
__device__ __forceinline__ void cp_async16(uint32_t s, const void* g) {
    asm volatile("cp.async.cg.shared.global [%0], [%1], 16;" :: "r"(s), "l"(g));
}
#define CP_COMMIT() asm volatile("cp.async.commit_group;" ::: "memory")
#define CP_WAIT2()  asm volatile("cp.async.wait_group 2;" ::: "memory")
#define CP_WAIT0()  asm volatile("cp.async.wait_group 0;" ::: "memory")

__device__ __forceinline__ void ldsm4(uint32_t (&r)[4], uint32_t addr) {
    asm volatile("ldmatrix.sync.aligned.m8n8.x4.shared.b16 {%0,%1,%2,%3}, [%4];"
                 : "=r"(r[0]), "=r"(r[1]), "=r"(r[2]), "=r"(r[3]) : "r"(addr));
}
__device__ __forceinline__ void mma16816(float (&c)[4], const uint32_t (&a)[4],
                                         uint32_t b0, uint32_t b1) {
    asm volatile("mma.sync.aligned.m16n8k16.row.col.f32.f16.f16.f32 "
                 "{%0,%1,%2,%3}, {%4,%5,%6,%7}, {%8,%9}, {%0,%1,%2,%3};"
                 : "+f"(c[0]), "+f"(c[1]), "+f"(c[2]), "+f"(c[3])
                 : "r"(a[0]), "r"(a[1]), "r"(a[2]), "r"(a[3]), "r"(b0), "r"(b1));
}
__device__ __forceinline__ uint32_t pack2h(float a, float b) {
    __half2 h = make_half2(__float2half_rn(a), __float2half_rn(b));
    return *reinterpret_cast<uint32_t*>(&h);
}

// Fold one 4x4 complex rep entry from 32 multivector coords; all table indices
// are unroll-constants over a local constexpr object -> pure signed-FADD chain.
__device__ __forceinline__ void rep_entry(const float (&v)[32], int idx,
                                          float& rr_out, float& ii_out) {
    constexpr Tables TBc{};
    float rr = 0.f, ii = 0.f;
#pragma unroll
    for (int e = 0; e < 8; e++) {
        const int a  = TBc.fw_a[idx][e];
        const int ph = TBc.fw_ph[idx][e];
        if      (ph == 0) rr += v[a];
        else if (ph == 1) ii += v[a];
        else if (ph == 2) rr -= v[a];
        else              ii -= v[a];
    }
    rr_out = rr; ii_out = ii;
}

// ---------------- pre-kernels ----------------
// x[b,f,0..31] -> X matrix entries; A2[4b+r, u*512 + f*4 + t]
__global__ __launch_bounds__(256) void k_build_A(const float* __restrict__ x) {
    unsigned tau = blockIdx.x * blockDim.x + threadIdx.x;   // 0 .. 524287
    unsigned b = tau >> 7, f = tau & 127u;
    float xv[32];
    const float4* xp = (const float4*)(x + ((size_t)b * 128 + f) * 32);
#pragma unroll
    for (int q = 0; q < 8; q++) {
        float4 v = xp[q];
        xv[q * 4 + 0] = v.x; xv[q * 4 + 1] = v.y; xv[q * 4 + 2] = v.z; xv[q * 4 + 3] = v.w;
    }
#pragma unroll
    for (int r = 0; r < 4; r++) {
        float re[4], im[4];
#pragma unroll
        for (int t = 0; t < 4; t++)
            rep_entry(xv, r * 4 + t, re[t], im[t]);
        size_t row = (size_t)(b * 4 + r) * GK;
        uint2 pre = make_uint2(pack2h(re[0], re[1]), pack2h(re[2], re[3]));
        uint2 pim = make_uint2(pack2h(im[0], im[1]), pack2h(im[2], im[3]));
        *(uint2*)(g_A2 + row + f * 4)       = pre;
        *(uint2*)(g_A2 + row + 512 + f * 4) = pim;
    }
}

// W[o,f,0..31] -> Wm; B2[n = o*8 + c*2 + v, u*512 + f*4 + t]
__global__ void k_build_w2(const float* __restrict__ w) {
    unsigned tau = blockIdx.x * blockDim.x + threadIdx.x;   // 0 .. 16383
    unsigned o = tau >> 7, f = tau & 127u;
    float wv[32];
    const float4* wp = (const float4*)(w + ((size_t)o * 128 + f) * 32);
#pragma unroll
    for (int q = 0; q < 8; q++) {
        float4 v = wp[q];
        wv[q * 4 + 0] = v.x; wv[q * 4 + 1] = v.y; wv[q * 4 + 2] = v.z; wv[q * 4 + 3] = v.w;
    }
    float re[4][4], im[4][4];   // [t][c]
#pragma unroll
    for (int t = 0; t < 4; t++)
#pragma unroll
        for (int c = 0; c < 4; c++)
            rep_entry(wv, t * 4 + c, re[t][c], im[t][c]);
#pragma unroll
    for (int c = 0; c < 4; c++)
#pragma unroll
        for (int v = 0; v < 2; v++) {
            size_t row = (size_t)(o * 8 + c * 2 + v) * GK;
            float u0[4], u1[4];
#pragma unroll
            for (int t = 0; t < 4; t++) {
                u0[t] = v ? im[t][c] :  re[t][c];
                u1[t] = v ? re[t][c] : -im[t][c];
            }
            *(uint2*)(g_B2 + row + f * 4)       = make_uint2(pack2h(u0[0], u0[1]), pack2h(u0[2], u0[3]));
            *(uint2*)(g_B2 + row + 512 + f * 4) = make_uint2(pack2h(u1[0], u1[1]), pack2h(u1[2], u1[3]));
        }
}

// ---------------- GEMM (mma.sync fp16) with fused epilogue ----------------
__device__ __forceinline__ void load_stage(uint32_t sbase, int slot, int m0, int n0,
                                           int k0, int tid) {
    const uint32_t so = sbase + slot * STAGE_BYTES;
    const __half* srcs[2] = {g_A2, g_B2};
    const int rows[2] = {m0, n0};
#pragma unroll
    for (int t2 = 0; t2 < 2; t2++) {
        const char* gb = (const char*)(srcs[t2] + (size_t)rows[t2] * GK + k0);
        uint32_t sdst = so + t2 * TILE_BYTES;
#pragma unroll
        for (int j = 0; j < 2; j++) {
            int chunk = tid * 2 + j;          // 0..511
            int r = chunk >> 2;               // row 0..127
            int cc = chunk & 3;               // 16B chunk in row
            cp_async16(sdst + r * ROW_BYTES + cc * 16,
                       gb + (size_t)r * (GK * 2) + cc * 16);
        }
    }
}

__global__ __launch_bounds__(256, 2) void gemm_kernel(float* __restrict__ out) {
    extern __shared__ char smem[];
    const uint32_t sb = smem_u32(smem);
    const int tid = threadIdx.x;
    const int wid = tid >> 5;
    const int lane = tid & 31;
    const int warp_m = wid & 1;               // 2 x 64 rows
    const int warp_n = wid >> 1;              // 4 x 32 cols
    const int m0 = blockIdx.y * BM;
    const int n0 = blockIdx.x * BN;

    float acc[4][4][4];
#pragma unroll
    for (int a = 0; a < 4; a++)
#pragma unroll
        for (int b = 0; b < 4; b++)
#pragma unroll
            for (int c = 0; c < 4; c++) acc[a][b][c] = 0.f;

    for (int s = 0; s < STAGES - 1; s++) {
        load_stage(sb, s, m0, n0, s * BK, tid);
        CP_COMMIT();
    }

    const int lrow = lane & 15;
    const int lhalf = lane >> 4;

    for (int t = 0; t < KTILES; t++) {
        CP_WAIT2();
        __syncthreads();

        if (t + STAGES - 1 < KTILES)
            load_stage(sb, (t + STAGES - 1) & 3, m0, n0, (t + STAGES - 1) * BK, tid);
        CP_COMMIT();

        const uint32_t st = sb + (t & 3) * STAGE_BYTES;
        const uint32_t Ah = st;
        const uint32_t Bh = st + TILE_BYTES;

#pragma unroll
        for (int ks = 0; ks < 2; ks++) {
            const int cc = ks * 2 + lhalf;
            uint32_t a[4][4];
#pragma unroll
            for (int mt = 0; mt < 4; mt++) {
                const int r = warp_m * 64 + mt * 16 + lrow;
                ldsm4(a[mt], Ah + r * ROW_BYTES + cc * 16);
            }
            uint32_t b0[4], b1[4];
#pragma unroll
            for (int np = 0; np < 2; np++) {
                const int r = warp_n * 32 + np * 16 + lrow;
                uint32_t q[4];
                ldsm4(q, Bh + r * ROW_BYTES + cc * 16);
                b0[2 * np] = q[0]; b0[2 * np + 1] = q[1];
                b1[2 * np] = q[2]; b1[2 * np + 1] = q[3];
            }
#pragma unroll
            for (int mt = 0; mt < 4; mt++)
#pragma unroll
                for (int nt = 0; nt < 4; nt++)
                    mma16816(acc[mt][nt], a[mt], b0[nt], b1[nt]);
        }
        __syncthreads();
    }

    // drain async pipe before repurposing SMEM
    CP_WAIT0();
    __syncthreads();

    // ---- fused epilogue ----
    float* cs = (float*)smem;
    const int gid = lane >> 2;
    const int qid = lane & 3;
#pragma unroll
    for (int mt = 0; mt < 4; mt++) {
        const int r0 = warp_m * 64 + mt * 16 + gid;
        const int r1 = r0 + 8;
#pragma unroll
        for (int nt = 0; nt < 4; nt++) {
            const int col = warp_n * 32 + nt * 8 + qid * 2;
            cs[r0 * EPI_STRIDE + col]     = acc[mt][nt][0];
            cs[r0 * EPI_STRIDE + col + 1] = acc[mt][nt][1];
            cs[r1 * EPI_STRIDE + col]     = acc[mt][nt][2];
            cs[r1 * EPI_STRIDE + col + 1] = acc[mt][nt][3];
        }
    }
    __syncthreads();

    constexpr Tables TBc{};
    const int b_base = m0 >> 2;    // global batch base of this tile
    const int o_base = n0 >> 3;    // global o base of this tile
#pragma unroll
    for (int it = 0; it < 2; it++) {
        const int blk = tid * 2 + it;          // 0..511
        const int b_local = blk >> 4;          // 0..31
        const int o_local = blk & 15;          // 0..15
        float blkv[4][8];
#pragma unroll
        for (int r = 0; r < 4; r++) {
            const float* rp = cs + (b_local * 4 + r) * EPI_STRIDE + o_local * 8;
#pragma unroll
            for (int c8 = 0; c8 < 8; c8++) blkv[r][c8] = rp[c8];
        }
        float y[32];
        float ssum = 0.f;
#pragma unroll
        for (int a = 0; a < 32; a++) {
            float s = 0.f;
#pragma unroll
            for (int c = 0; c < 4; c++) {
                const int   ir = TBc.inv_row[a][c];   // compile-time
                const int   ic = TBc.inv_c8[a][c];    // compile-time
                const float sg = TBc.inv_sgn[a][c];   // compile-time immediate
                s += sg * blkv[ir][ic];
            }
            y[a] = s;
            ssum += s * s;
        }
        const float inv = rsqrtf(ssum + 1e-6f);
        float* op = out + (size_t)(b_base + b_local) * 4096 + (o_base + o_local) * 32;
#pragma unroll
        for (int a = 0; a < 32; a += 4)
            *(float4*)(op + a) = make_float4(y[a] * inv, y[a + 1] * inv,
                                             y[a + 2] * inv, y[a + 3] * inv);
    }
}

// ---------------- launch ----------------
extern "C" void kernel_launch(void* const* d_in, const int* in_sizes, int n_in,
                              void* d_out, int out_size) {
    (void)in_sizes; (void)n_in; (void)out_size;
    const float* x = (const float*)d_in[0];
    const float* w = (const float*)d_in[1];
    float* out = (float*)d_out;

    k_build_A<<<524288 / 256, 256>>>(x);
    k_build_w2<<<16384 / 256, 256>>>(w);

    static bool attr_set = false;
    if (!attr_set) {
        cudaFuncSetAttribute(gemm_kernel, cudaFuncAttributeMaxDynamicSharedMemorySize,
                             SMEM_BYTES);
        attr_set = true;
    }
    gemm_kernel<<<dim3(GN / BN, GM / BM), 256, SMEM_BYTES>>>(out);
}